// round 8
// baseline (speedup 1.0000x reference)
#include <cuda_runtime.h>
#include <stdint.h>

#define NN    50000
#define HID   128
#define NREL  3
#define EMAX  800000

// ---------------- scratch (device globals; 16B-aligned) ----------------------
__device__ __align__(16) float g_h  [(size_t)NN * HID];        // current features
__device__ __align__(16) float g_hw [NREL][(size_t)NN * HID];  // (h @ w[r]) * dis[r]
__device__ __align__(16) float g_dis[NREL][NN];                // rsqrt(deg+1)
__device__ __align__(16) int   g_deg[NREL][NN];
__device__ __align__(16) int   g_off[NREL][NN + 1];            // CSR row offsets
__device__ __align__(16) int   g_cur[NREL][NN];                // fill cursors
__device__ __align__(16) int   g_csr[NREL][EMAX];              // src sorted by dst

// ---------------- packed f32x2 helpers ----------------------------------------
__device__ __forceinline__ void ffma2(unsigned long long& d,
                                      unsigned long long a,
                                      unsigned long long b) {
    asm("fma.rn.f32x2 %0, %1, %2, %0;" : "+l"(d) : "l"(a), "l"(b));
}
__device__ __forceinline__ float2 unpack2(unsigned long long v) {
    float2 r;
    asm("mov.b64 {%0, %1}, %2;" : "=f"(r.x), "=f"(r.y) : "l"(v));
    return r;
}

// ---------------- degree ------------------------------------------------------
__global__ void zero_deg_kernel() {
    int i = blockIdx.x * blockDim.x + threadIdx.x;
    if (i < NREL * NN) ((int*)g_deg)[i] = 0;
}

__global__ void count_kernel(const int* __restrict__ edges, int E) {
    const int r = blockIdx.y;
    const int* dst = edges + (size_t)(2 * r + 1) * E;
    for (int e = blockIdx.x * blockDim.x + threadIdx.x; e < E;
         e += gridDim.x * blockDim.x) {
        int d = dst[e];
        if ((unsigned)d < NN) atomicAdd(&g_deg[r][d], 1);
    }
}

__global__ __launch_bounds__(1024) void scan_kernel() {
    const int r = blockIdx.x;
    __shared__ int warp_sums[32];
    __shared__ int s_carry;
    if (threadIdx.x == 0) s_carry = 0;
    __syncthreads();
    const int lane = threadIdx.x & 31;
    const int wid  = threadIdx.x >> 5;
    for (int base = 0; base < NN; base += 1024) {
        int i = base + (int)threadIdx.x;
        int v = (i < NN) ? g_deg[r][i] : 0;
        int x = v;
#pragma unroll
        for (int o = 1; o < 32; o <<= 1) {
            int y = __shfl_up_sync(0xffffffffu, x, o);
            if (lane >= o) x += y;
        }
        if (lane == 31) warp_sums[wid] = x;
        __syncthreads();
        if (threadIdx.x < 32) {
            int w = warp_sums[threadIdx.x];
#pragma unroll
            for (int o = 1; o < 32; o <<= 1) {
                int y = __shfl_up_sync(0xffffffffu, w, o);
                if ((int)threadIdx.x >= o) w += y;
            }
            warp_sums[threadIdx.x] = w;
        }
        __syncthreads();
        int incl = x + (wid > 0 ? warp_sums[wid - 1] : 0);
        int excl = incl - v + s_carry;
        if (i < NN) { g_off[r][i] = excl; g_cur[r][i] = excl; }
        int block_total = warp_sums[31];
        __syncthreads();
        if (threadIdx.x == 0) s_carry += block_total;
        __syncthreads();
    }
    if (threadIdx.x == 0) g_off[r][NN] = s_carry;
}

__global__ void dis_kernel() {
    int i = blockIdx.x * blockDim.x + threadIdx.x;
    if (i < NREL * NN) {
        int c = ((const int*)g_deg)[i];
        ((float*)g_dis)[i] = rsqrtf((float)c + 1.0f);
    }
}

__global__ void fill_csr_kernel(const int* __restrict__ edges, int E) {
    const int r = blockIdx.y;
    const int* src = edges + (size_t)(2 * r) * E;
    const int* dst = src + E;
    for (int e = blockIdx.x * blockDim.x + threadIdx.x; e < E;
         e += gridDim.x * blockDim.x) {
        int s = src[e], d = dst[e];
        if ((unsigned)d < NN && (unsigned)s < NN) {
            int pos = atomicAdd(&g_cur[r][d], 1);
            g_csr[r][pos] = s;
        }
    }
}

// ---------------- register-tiled SGEMM, packed f32x2 FMA ----------------------
// MODE 0: g_h    = relu(Aext @ B + bias)                (embedder, scalar loads)
// MODE 1: g_hw[r]= (g_h @ B[r]) * dis[r][row]           (relation GEMMs, float4)
// MODE 2: Cext   = g_h @ B + bias                       (final linear, float4)
template <int BM, int BN, int BK, int TM, int TN, int MODE>
__launch_bounds__(256)
__global__ void sgemm_kernel(const float* __restrict__ Aext,
                             const float* __restrict__ Bmat,
                             const float* __restrict__ bias,
                             float* __restrict__ Cext,
                             int M, int K) {
    constexpr bool VEC = (MODE != 0);   // K==128 paths, 16B-aligned
    const int r = blockIdx.y;
    const float* A = (MODE == 0) ? Aext : g_h;
    const float* B = Bmat + (size_t)r * K * BN;

    __shared__ float As[BK][BM + 4];       // transposed A tile (row pairs contiguous)
    __shared__ float Bs[BK][2 * BN];       // duplicated B tile: {v, v} pairs

    const int tid  = threadIdx.x;
    constexpr int TC = BN / TN;
    const int trow = tid / TC;
    const int tcol = tid % TC;
    const int rowBase = blockIdx.x * BM;

    unsigned long long acc[TM / 2][TN];    // packed row-pair accumulators
#pragma unroll
    for (int i = 0; i < TM / 2; i++)
#pragma unroll
        for (int j = 0; j < TN; j++) acc[i][j] = 0ull;

    const int ntiles = (K + BK - 1) / BK;

    // prefetch registers
    constexpr int AF4 = VEC ? (BM * BK) / (4 * 256) : 1;
    constexpr int BF4 = VEC ? (BK * BN) / (4 * 256) : 1;
    constexpr int ASC = VEC ? 1 : (BM * BK) / 256;
    constexpr int BSC = VEC ? 1 : (BK * BN) / 256;
    float4 va[AF4], vb[BF4];
    float  sa[ASC], sb[BSC];

    auto fetch = [&](int k0) {
        if (VEC) {
#pragma unroll
            for (int v = 0; v < AF4; v++) {
                int g   = tid + v * 256;
                int row = g / (BK / 4);
                int c4  = g % (BK / 4);
                int gr  = rowBase + row; if (gr >= M) gr = M - 1;
                va[v] = *(const float4*)&A[(size_t)gr * K + k0 + c4 * 4];
            }
#pragma unroll
            for (int v = 0; v < BF4; v++) {
                int g   = tid + v * 256;
                int row = g / (BN / 4);
                int c4  = g % (BN / 4);
                vb[v] = *(const float4*)&B[(size_t)(k0 + row) * BN + c4 * 4];
            }
        } else {
#pragma unroll
            for (int v = 0; v < ASC; v++) {
                int g  = tid + v * 256;
                int rr = g / BK, cc = g % BK;
                int gr = rowBase + rr; if (gr >= M) gr = M - 1;
                int gc = k0 + cc;
                sa[v] = (gc < K) ? A[(size_t)gr * K + gc] : 0.f;
            }
#pragma unroll
            for (int v = 0; v < BSC; v++) {
                int g  = tid + v * 256;
                int rr = g / BN, cc = g % BN;
                int gk = k0 + rr;
                sb[v] = (gk < K) ? B[(size_t)gk * BN + cc] : 0.f;
            }
        }
    };
    auto commit = [&]() {
        if (VEC) {
#pragma unroll
            for (int v = 0; v < AF4; v++) {
                int g   = tid + v * 256;
                int row = g / (BK / 4);
                int c4  = g % (BK / 4);
                As[c4 * 4 + 0][row] = va[v].x;
                As[c4 * 4 + 1][row] = va[v].y;
                As[c4 * 4 + 2][row] = va[v].z;
                As[c4 * 4 + 3][row] = va[v].w;
            }
#pragma unroll
            for (int v = 0; v < BF4; v++) {
                int g   = tid + v * 256;
                int row = g / (BN / 4);
                int c4  = g % (BN / 4);
                float2* p = (float2*)&Bs[row][c4 * 8];
                p[0] = make_float2(vb[v].x, vb[v].x);
                p[1] = make_float2(vb[v].y, vb[v].y);
                p[2] = make_float2(vb[v].z, vb[v].z);
                p[3] = make_float2(vb[v].w, vb[v].w);
            }
        } else {
#pragma unroll
            for (int v = 0; v < ASC; v++) {
                int g  = tid + v * 256;
                As[g % BK][g / BK] = sa[v];
            }
#pragma unroll
            for (int v = 0; v < BSC; v++) {
                int g  = tid + v * 256;
                int rr = g / BN, cc = g % BN;
                float2* p = (float2*)&Bs[rr][cc * 2];
                p[0] = make_float2(sb[v], sb[v]);
            }
        }
    };

    fetch(0);
    commit();
    __syncthreads();

    for (int t = 0; t < ntiles; t++) {
        if (t + 1 < ntiles) fetch((t + 1) * BK);
#pragma unroll
        for (int kk = 0; kk < BK; kk++) {
            unsigned long long ap[TM / 2], bd[TN];
#pragma unroll
            for (int i = 0; i < TM / 2; i++)
                ap[i] = *(const unsigned long long*)&As[kk][trow * TM + 2 * i];
#pragma unroll
            for (int j = 0; j < TN; j++)
                bd[j] = *(const unsigned long long*)&Bs[kk][2 * (tcol * TN + j)];
#pragma unroll
            for (int i = 0; i < TM / 2; i++)
#pragma unroll
                for (int j = 0; j < TN; j++)
                    ffma2(acc[i][j], ap[i], bd[j]);
        }
        __syncthreads();
        if (t + 1 < ntiles) {
            commit();
            __syncthreads();
        }
    }

#pragma unroll
    for (int i = 0; i < TM / 2; i++) {
#pragma unroll
        for (int half = 0; half < 2; half++) {
            int gr = rowBase + trow * TM + 2 * i + half;
            if (gr >= M) continue;
            float dscale = (MODE == 1) ? g_dis[r][gr] : 1.f;
#pragma unroll
            for (int j = 0; j < TN; j++) {
                float2 p = unpack2(acc[i][j]);
                float v = half ? p.y : p.x;
                int gc = tcol * TN + j;
                if (MODE == 0) {
                    g_h[(size_t)gr * BN + gc] = fmaxf(v + bias[gc], 0.f);
                } else if (MODE == 1) {
                    g_hw[r][(size_t)gr * BN + gc] = v * dscale;
                } else {
                    Cext[(size_t)gr * BN + gc] = v + bias[gc];
                }
            }
        }
    }
}

// ---------------- CSR gather: warp per node, fused self+bias+relu ------------
__launch_bounds__(256)
__global__ void gather_kernel(const float* __restrict__ bias) {
    const int node = (blockIdx.x * blockDim.x + threadIdx.x) >> 5;
    const int lane = threadIdx.x & 31;
    if (node >= NN) return;
    const int c0 = lane * 4;

    float4 tot;
    tot.x = bias[c0 + 0] + bias[HID + c0 + 0] + bias[2 * HID + c0 + 0];
    tot.y = bias[c0 + 1] + bias[HID + c0 + 1] + bias[2 * HID + c0 + 1];
    tot.z = bias[c0 + 2] + bias[HID + c0 + 2] + bias[2 * HID + c0 + 2];
    tot.w = bias[c0 + 3] + bias[HID + c0 + 3] + bias[2 * HID + c0 + 3];

#pragma unroll
    for (int r = 0; r < NREL; r++) {
        const float4* hw4 = (const float4*)g_hw[r];
        float4 a = hw4[(size_t)node * (HID / 4) + lane];   // self loop (pre-scaled)
        const int beg = g_off[r][node];
        const int end = g_off[r][node + 1];
        const int* __restrict__ csr = g_csr[r];
        for (int t = beg; t < end; t += 32) {
            int idx = (t + lane < end) ? csr[t + lane] : 0;
            int n = end - t; if (n > 32) n = 32;
            for (int j = 0; j < n; j++) {
                int s = __shfl_sync(0xffffffffu, idx, j);
                float4 v = hw4[(size_t)s * (HID / 4) + lane];
                a.x += v.x; a.y += v.y; a.z += v.z; a.w += v.w;
            }
        }
        float dd = g_dis[r][node];
        tot.x += a.x * dd; tot.y += a.y * dd;
        tot.z += a.z * dd; tot.w += a.w * dd;
    }
    tot.x = fmaxf(tot.x, 0.f);
    tot.y = fmaxf(tot.y, 0.f);
    tot.z = fmaxf(tot.z, 0.f);
    tot.w = fmaxf(tot.w, 0.f);
    ((float4*)g_h)[(size_t)node * (HID / 4) + lane] = tot;
}

// ---------------- launch ------------------------------------------------------
extern "C" void kernel_launch(void* const* d_in, const int* in_sizes, int n_in,
                              void* d_out, int out_size) {
    const float* x     = (const float*)d_in[0];
    const int*   ei    = (const int*)d_in[1];   // int32 (JAX x64 disabled)
    const float* emb_w = (const float*)d_in[2];
    const float* emb_b = (const float*)d_in[3];
    const float* w0    = (const float*)d_in[4];
    const float* b0    = (const float*)d_in[5];
    const float* w1    = (const float*)d_in[6];
    const float* b1    = (const float*)d_in[7];
    const float* lin_w = (const float*)d_in[8];
    const float* lin_b = (const float*)d_in[9];
    float* out = (float*)d_out;

    const int E = in_sizes[1] / (2 * NREL);
    const int M = NN;

    // CSR build (shared by both layers)
    zero_deg_kernel<<<(NREL * NN + 255) / 256, 256>>>();
    count_kernel<<<dim3(256, NREL), 256>>>(ei, E);
    scan_kernel<<<NREL, 1024>>>();
    dis_kernel<<<(NREL * NN + 255) / 256, 256>>>();
    fill_csr_kernel<<<dim3(256, NREL), 256>>>(ei, E);

    const int gather_blocks = (NN * 32 + 255) / 256;   // warp per node

    // embedder: h = relu(x @ emb_w + emb_b)
    sgemm_kernel<64, 128, 16, 4, 8, 0>
        <<<dim3((M + 63) / 64, 1), 256>>>(x, emb_w, emb_b, nullptr, M, 300);

    // layer 0
    sgemm_kernel<128, 128, 16, 8, 8, 1>
        <<<dim3((M + 127) / 128, NREL), 256>>>(nullptr, w0, nullptr, nullptr, M, HID);
    gather_kernel<<<gather_blocks, 256>>>(b0);

    // layer 1
    sgemm_kernel<128, 128, 16, 8, 8, 1>
        <<<dim3((M + 127) / 128, NREL), 256>>>(nullptr, w1, nullptr, nullptr, M, HID);
    gather_kernel<<<gather_blocks, 256>>>(b1);

    // final linear: out = h @ lin_w + lin_b
    sgemm_kernel<128, 64, 16, 8, 4, 2>
        <<<dim3((M + 127) / 128, 1), 256>>>(nullptr, lin_w, lin_b, out, M, HID);
}

// round 10
// speedup vs baseline: 1.9430x; 1.9430x over previous
#include <cuda_runtime.h>
#include <stdint.h>

#define NN    50000
#define HID   128
#define NREL  3
#define EMAX  800000

// ---------------- scratch (device globals; 16B-aligned) ----------------------
__device__ __align__(16) float g_h  [(size_t)NN * HID];        // current features
__device__ __align__(16) float g_hw [NREL][(size_t)NN * HID];  // (h @ w[r]) * dis[r]
__device__ __align__(16) int   g_deg[NREL][NN];
__device__ __align__(16) int   g_off[NREL][NN + 1];            // CSR row offsets
__device__ __align__(16) int   g_cur[NREL][NN];                // fill cursors
__device__ __align__(16) int   g_csr[NREL][EMAX];              // src sorted by dst

// ---------------- GEMM body: double-buffered, float4 loads --------------------
// MODE 0: g_h    = relu(A @ B + bias)          (embedder)
// MODE 1: g_hw[r]= (g_h @ B[r]) * rsqrt(deg+1) (relation GEMMs)
// MODE 2: Cext   = g_h @ B + bias              (final linear)
// Requires: K % BK == 0, K % 4 == 0, A rows 16B-aligned.
template <int BM, int BN, int BK, int TM, int TN, int MODE>
__device__ __forceinline__ void sgemm_body(const float* __restrict__ Aext,
                                           const float* __restrict__ Bmat,
                                           const float* __restrict__ bias,
                                           float* __restrict__ Cext,
                                           int M, int K, int r, int tilex) {
    const float* A = (MODE == 0) ? Aext : g_h;
    const float* B = Bmat + (size_t)r * K * BN;

    // 16B alignment is mandatory: these kernels may share smem with other
    // block-role branches (scan) whose smaller objects would otherwise shift
    // the base to a 4B boundary and break LDS.128 / STS.128.
    __shared__ __align__(16) float As[2][BK][BM + 4];   // transposed A (ping-pong)
    __shared__ __align__(16) float Bs[2][BK][BN];

    const int tid  = threadIdx.x;
    constexpr int TC = BN / TN;
    const int trow = tid / TC;
    const int tcol = tid % TC;
    const int rowBase = tilex * BM;

    float acc[TM][TN];
#pragma unroll
    for (int i = 0; i < TM; i++)
#pragma unroll
        for (int j = 0; j < TN; j++) acc[i][j] = 0.f;

    constexpr int ACNT = BM * BK / 4;   // float4s per A tile
    constexpr int BCNT = BK * BN / 4;
    constexpr int AF4  = (ACNT + 255) / 256;
    constexpr int BF4  = (BCNT + 255) / 256;
    float4 va[AF4], vb[BF4];

    const int ntiles = K / BK;

    auto fetch = [&](int k0) {
#pragma unroll
        for (int v = 0; v < AF4; v++) {
            int g = tid + v * 256;
            if ((ACNT % 256 == 0) || g < ACNT) {
                int row = g / (BK / 4), c4 = g % (BK / 4);
                int gr = rowBase + row; if (gr >= M) gr = M - 1;
                va[v] = *(const float4*)&A[(size_t)gr * K + k0 + c4 * 4];
            }
        }
#pragma unroll
        for (int v = 0; v < BF4; v++) {
            int g = tid + v * 256;
            if ((BCNT % 256 == 0) || g < BCNT) {
                int row = g / (BN / 4), c4 = g % (BN / 4);
                vb[v] = *(const float4*)&B[(size_t)(k0 + row) * BN + c4 * 4];
            }
        }
    };
    auto commit = [&](int buf) {
#pragma unroll
        for (int v = 0; v < AF4; v++) {
            int g = tid + v * 256;
            if ((ACNT % 256 == 0) || g < ACNT) {
                int row = g / (BK / 4), c4 = g % (BK / 4);
                As[buf][c4 * 4 + 0][row] = va[v].x;
                As[buf][c4 * 4 + 1][row] = va[v].y;
                As[buf][c4 * 4 + 2][row] = va[v].z;
                As[buf][c4 * 4 + 3][row] = va[v].w;
            }
        }
#pragma unroll
        for (int v = 0; v < BF4; v++) {
            int g = tid + v * 256;
            if ((BCNT % 256 == 0) || g < BCNT) {
                int row = g / (BN / 4), c4 = g % (BN / 4);
                *(float4*)&Bs[buf][row][c4 * 4] = vb[v];
            }
        }
    };

    fetch(0);
    commit(0);
    __syncthreads();

    for (int t = 0; t < ntiles; t++) {
        const int cur = t & 1;
        if (t + 1 < ntiles) fetch((t + 1) * BK);
#pragma unroll
        for (int kk = 0; kk < BK; kk++) {
            float a[TM], b[TN];
#pragma unroll
            for (int i = 0; i < TM; i++) a[i] = As[cur][kk][trow * TM + i];
#pragma unroll
            for (int j = 0; j < TN; j++) b[j] = Bs[cur][kk][tcol * TN + j];
#pragma unroll
            for (int i = 0; i < TM; i++)
#pragma unroll
                for (int j = 0; j < TN; j++)
                    acc[i][j] = fmaf(a[i], b[j], acc[i][j]);
        }
        if (t + 1 < ntiles) commit(cur ^ 1);
        __syncthreads();
    }

#pragma unroll
    for (int i = 0; i < TM; i++) {
        int gr = rowBase + trow * TM + i;
        if (gr >= M) continue;
        float dscale = 1.f;
        if (MODE == 1) dscale = rsqrtf((float)g_deg[r][gr] + 1.0f);
#pragma unroll
        for (int j = 0; j < TN; j++) {
            int gc = tcol * TN + j;
            float v = acc[i][j];
            if (MODE == 0) {
                g_h[(size_t)gr * BN + gc] = fmaxf(v + bias[gc], 0.f);
            } else if (MODE == 1) {
                g_hw[r][(size_t)gr * BN + gc] = v * dscale;
            } else {
                Cext[(size_t)gr * BN + gc] = v + bias[gc];
            }
        }
    }
}

// ---------------- CSR-build device bodies --------------------------------------
__device__ void count_body(const int* __restrict__ ei, int E, int bid, int nb) {
#pragma unroll
    for (int r = 0; r < NREL; r++) {
        const int* dst = ei + (size_t)(2 * r + 1) * E;
        for (int e = bid * 256 + (int)threadIdx.x; e < E; e += nb * 256) {
            int d = dst[e];
            if ((unsigned)d < NN) atomicAdd(&g_deg[r][d], 1);
        }
    }
}

__device__ void fill_body(const int* __restrict__ ei, int E, int bid, int nb) {
#pragma unroll
    for (int r = 0; r < NREL; r++) {
        const int* src = ei + (size_t)(2 * r) * E;
        const int* dst = src + E;
        for (int e = bid * 256 + (int)threadIdx.x; e < E; e += nb * 256) {
            int s = src[e], d = dst[e];
            if ((unsigned)d < NN && (unsigned)s < NN) {
                int pos = atomicAdd(&g_cur[r][d], 1);
                g_csr[r][pos] = s;
            }
        }
    }
}

// 256-thread block-sequential exclusive scan over one relation's degrees
__device__ void scan_body(int r) {
    __shared__ __align__(16) int wsum[8];
    __shared__ int carry;
    const int tid = threadIdx.x;
    const int lane = tid & 31;
    const int wid  = tid >> 5;
    if (tid == 0) carry = 0;
    __syncthreads();
    for (int base = 0; base < NN; base += 256) {
        int i = base + tid;
        int v = (i < NN) ? g_deg[r][i] : 0;
        int x = v;
#pragma unroll
        for (int o = 1; o < 32; o <<= 1) {
            int y = __shfl_up_sync(0xffffffffu, x, o);
            if (lane >= o) x += y;
        }
        if (lane == 31) wsum[wid] = x;
        __syncthreads();
        if (tid < 8) {
            int w = wsum[tid];
#pragma unroll
            for (int o = 1; o < 8; o <<= 1) {
                int y = __shfl_up_sync(0x000000ffu, w, o);
                if (tid >= o) w += y;
            }
            wsum[tid] = w;
        }
        __syncthreads();
        int excl = x - v + (wid > 0 ? wsum[wid - 1] : 0) + carry;
        if (i < NN) { g_off[r][i] = excl; g_cur[r][i] = excl; }
        int total = wsum[7];
        __syncthreads();
        if (tid == 0) carry += total;
        __syncthreads();
    }
    if (tid == 0) g_off[r][NN] = carry;
}

// ---------------- kernels -------------------------------------------------------
#define EMB_TILES 782   /* ceil(50000/64) */
#define REL_TILES 391   /* ceil(50000/128) */
#define CNT_BLKS  128
#define FILL_BLKS 192

__global__ void zero_deg_kernel() {
    int i = blockIdx.x * blockDim.x + threadIdx.x;
    if (i < NREL * NN) ((int*)g_deg)[i] = 0;
}

// K2: embedder GEMM (782 blocks) + degree count (128 blocks)
__global__ __launch_bounds__(256)
void k2_emb_count(const float* __restrict__ x, const float* __restrict__ emb_w,
                  const float* __restrict__ emb_b,
                  const int* __restrict__ ei, int E) {
    if (blockIdx.x < EMB_TILES)
        sgemm_body<64, 128, 20, 4, 8, 0>(x, emb_w, emb_b, nullptr, NN, 300, 0, blockIdx.x);
    else
        count_body(ei, E, blockIdx.x - EMB_TILES, CNT_BLKS);
}

// K3: relation GEMMs r=0,1 (782 blocks) + scan (3 blocks)
__global__ __launch_bounds__(256)
void k3_rel01_scan(const float* __restrict__ w) {
    int b = blockIdx.x;
    if (b < 2 * REL_TILES)
        sgemm_body<128, 128, 16, 8, 8, 1>(nullptr, w, nullptr, nullptr, NN, HID,
                                          b / REL_TILES, b % REL_TILES);
    else
        scan_body(b - 2 * REL_TILES);
}

// K4: relation GEMM r=2 (391 blocks) + CSR fill (192 blocks)
__global__ __launch_bounds__(256)
void k4_rel2_fill(const float* __restrict__ w, const int* __restrict__ ei, int E) {
    if (blockIdx.x < REL_TILES)
        sgemm_body<128, 128, 16, 8, 8, 1>(nullptr, w, nullptr, nullptr, NN, HID,
                                          2, blockIdx.x);
    else
        fill_body(ei, E, blockIdx.x - REL_TILES, FILL_BLKS);
}

// plain relation-GEMM launch (layer 1, all 3 relations)
__global__ __launch_bounds__(256)
void rel_gemm_kernel(const float* __restrict__ w) {
    sgemm_body<128, 128, 16, 8, 8, 1>(nullptr, w, nullptr, nullptr, NN, HID,
                                      blockIdx.y, blockIdx.x);
}

// final linear
__global__ __launch_bounds__(256)
void fin_gemm_kernel(const float* __restrict__ w, const float* __restrict__ b,
                     float* __restrict__ out) {
    sgemm_body<128, 64, 16, 8, 4, 2>(nullptr, w, b, out, NN, HID, 0, blockIdx.x);
}

// ---------------- CSR gather: warp per node, fused self+bias+relu ------------
__launch_bounds__(256)
__global__ void gather_kernel(const float* __restrict__ bias) {
    const int node = (blockIdx.x * blockDim.x + threadIdx.x) >> 5;
    const int lane = threadIdx.x & 31;
    if (node >= NN) return;
    const int c0 = lane * 4;

    float4 tot;
    tot.x = bias[c0 + 0] + bias[HID + c0 + 0] + bias[2 * HID + c0 + 0];
    tot.y = bias[c0 + 1] + bias[HID + c0 + 1] + bias[2 * HID + c0 + 1];
    tot.z = bias[c0 + 2] + bias[HID + c0 + 2] + bias[2 * HID + c0 + 2];
    tot.w = bias[c0 + 3] + bias[HID + c0 + 3] + bias[2 * HID + c0 + 3];

#pragma unroll
    for (int r = 0; r < NREL; r++) {
        const float4* hw4 = (const float4*)g_hw[r];
        float4 a = hw4[(size_t)node * (HID / 4) + lane];   // self loop (pre-scaled)
        const int beg = g_off[r][node];
        const int end = g_off[r][node + 1];
        const int* __restrict__ csr = g_csr[r];
        for (int t = beg; t < end; t += 32) {
            int idx = (t + lane < end) ? csr[t + lane] : 0;
            int n = end - t; if (n > 32) n = 32;
            for (int j = 0; j < n; j++) {
                int s = __shfl_sync(0xffffffffu, idx, j);
                float4 v = hw4[(size_t)s * (HID / 4) + lane];
                a.x += v.x; a.y += v.y; a.z += v.z; a.w += v.w;
            }
        }
        float dd = rsqrtf((float)g_deg[r][node] + 1.0f);
        tot.x += a.x * dd; tot.y += a.y * dd;
        tot.z += a.z * dd; tot.w += a.w * dd;
    }
    tot.x = fmaxf(tot.x, 0.f);
    tot.y = fmaxf(tot.y, 0.f);
    tot.z = fmaxf(tot.z, 0.f);
    tot.w = fmaxf(tot.w, 0.f);
    ((float4*)g_h)[(size_t)node * (HID / 4) + lane] = tot;
}

// ---------------- launch ------------------------------------------------------
extern "C" void kernel_launch(void* const* d_in, const int* in_sizes, int n_in,
                              void* d_out, int out_size) {
    const float* x     = (const float*)d_in[0];
    const int*   ei    = (const int*)d_in[1];   // int32 (JAX x64 disabled)
    const float* emb_w = (const float*)d_in[2];
    const float* emb_b = (const float*)d_in[3];
    const float* w0    = (const float*)d_in[4];
    const float* b0    = (const float*)d_in[5];
    const float* w1    = (const float*)d_in[6];
    const float* b1    = (const float*)d_in[7];
    const float* lin_w = (const float*)d_in[8];
    const float* lin_b = (const float*)d_in[9];
    float* out = (float*)d_out;

    const int E = in_sizes[1] / (2 * NREL);
    const int gather_blocks = (NN * 32 + 255) / 256;   // warp per node

    // stage 1: zero degree counters
    zero_deg_kernel<<<(NREL * NN + 255) / 256, 256>>>();

    // stage 2: embedder GEMM || degree count
    k2_emb_count<<<EMB_TILES + CNT_BLKS, 256>>>(x, emb_w, emb_b, ei, E);

    // stage 3: layer-0 relation GEMMs r=0,1 || offset scan
    k3_rel01_scan<<<2 * REL_TILES + NREL, 256>>>(w0);

    // stage 4: layer-0 relation GEMM r=2 || CSR fill
    k4_rel2_fill<<<REL_TILES + FILL_BLKS, 256>>>(w0, ei, E);

    // layer-0 aggregate
    gather_kernel<<<gather_blocks, 256>>>(b0);

    // layer 1
    rel_gemm_kernel<<<dim3(REL_TILES, NREL), 256>>>(w1);
    gather_kernel<<<gather_blocks, 256>>>(b1);

    // final linear
    fin_gemm_kernel<<<REL_TILES, 256>>>(lin_w, lin_b, out);
}

// round 11
// speedup vs baseline: 2.1721x; 1.1179x over previous
#include <cuda_runtime.h>
#include <stdint.h>

#define NN    50000
#define HID   128
#define NREL  3
#define EMAX  800000

// ---------------- scratch (device globals; 16B-aligned) ----------------------
__device__ __align__(16) float g_h  [(size_t)NN * HID];        // current features
__device__ __align__(16) float g_hw [NREL][(size_t)NN * HID];  // (h @ w[r]) * dis[r]
__device__ __align__(16) int   g_deg[NREL][NN];
__device__ __align__(16) int   g_off[NREL][NN + 1];            // CSR row offsets
__device__ __align__(16) int   g_cur[NREL][NN];                // fill cursors
__device__ __align__(16) int   g_csr[NREL][EMAX];              // src sorted by dst

// ---------------- GEMM body: single smem buffer + register prefetch -----------
// (round-5 proven structure: regs ~110, fetch(next) overlaps compute(cur))
// MODE 0: g_h    = relu(A @ B + bias)          (embedder)
// MODE 1: g_hw[r]= (g_h @ B[r]) * rsqrt(deg+1) (relation GEMMs)
// MODE 2: Cext   = g_h @ B + bias              (final linear)
// Requires: K % BK == 0, K % 4 == 0, BK % 4 == 0, A rows 16B-aligned.
template <int BM, int BN, int BK, int TM, int TN, int MODE>
__device__ __forceinline__ void sgemm_body(const float* __restrict__ Aext,
                                           const float* __restrict__ Bmat,
                                           const float* __restrict__ bias,
                                           float* __restrict__ Cext,
                                           int M, int K, int r, int tilex) {
    const float* A = (MODE == 0) ? Aext : g_h;
    const float* B = Bmat + (size_t)r * K * BN;

    // 16B alignment mandatory: hybrid kernels share smem layout with aux
    // branches whose small objects would otherwise shift the base.
    __shared__ __align__(16) float As[BK][BM + 4];   // transposed A tile
    __shared__ __align__(16) float Bs[BK][BN];

    const int tid  = threadIdx.x;
    constexpr int TC = BN / TN;
    const int trow = tid / TC;
    const int tcol = tid % TC;
    const int rowBase = tilex * BM;

    float acc[TM][TN];
#pragma unroll
    for (int i = 0; i < TM; i++)
#pragma unroll
        for (int j = 0; j < TN; j++) acc[i][j] = 0.f;

    constexpr int ACNT = BM * BK / 4;   // float4s per A tile
    constexpr int BCNT = BK * BN / 4;
    constexpr int AF4  = (ACNT + 255) / 256;
    constexpr int BF4  = (BCNT + 255) / 256;
    float4 va[AF4], vb[BF4];

    const int ntiles = K / BK;

    auto fetch = [&](int k0) {
#pragma unroll
        for (int v = 0; v < AF4; v++) {
            int g = tid + v * 256;
            if ((ACNT % 256 == 0) || g < ACNT) {
                int row = g / (BK / 4), c4 = g % (BK / 4);
                int gr = rowBase + row; if (gr >= M) gr = M - 1;
                va[v] = *(const float4*)&A[(size_t)gr * K + k0 + c4 * 4];
            }
        }
#pragma unroll
        for (int v = 0; v < BF4; v++) {
            int g = tid + v * 256;
            if ((BCNT % 256 == 0) || g < BCNT) {
                int row = g / (BN / 4), c4 = g % (BN / 4);
                vb[v] = *(const float4*)&B[(size_t)(k0 + row) * BN + c4 * 4];
            }
        }
    };
    auto commit = [&]() {
#pragma unroll
        for (int v = 0; v < AF4; v++) {
            int g = tid + v * 256;
            if ((ACNT % 256 == 0) || g < ACNT) {
                int row = g / (BK / 4), c4 = g % (BK / 4);
                As[c4 * 4 + 0][row] = va[v].x;
                As[c4 * 4 + 1][row] = va[v].y;
                As[c4 * 4 + 2][row] = va[v].z;
                As[c4 * 4 + 3][row] = va[v].w;
            }
        }
#pragma unroll
        for (int v = 0; v < BF4; v++) {
            int g = tid + v * 256;
            if ((BCNT % 256 == 0) || g < BCNT) {
                int row = g / (BN / 4), c4 = g % (BN / 4);
                *(float4*)&Bs[row][c4 * 4] = vb[v];
            }
        }
    };

    fetch(0);
    commit();
    __syncthreads();

    for (int t = 0; t < ntiles; t++) {
        if (t + 1 < ntiles) fetch((t + 1) * BK);
#pragma unroll
        for (int kk = 0; kk < BK; kk++) {
            float a[TM], b[TN];
#pragma unroll
            for (int i = 0; i < TM; i++) a[i] = As[kk][trow * TM + i];
#pragma unroll
            for (int j = 0; j < TN; j++) b[j] = Bs[kk][tcol * TN + j];
#pragma unroll
            for (int i = 0; i < TM; i++)
#pragma unroll
                for (int j = 0; j < TN; j++)
                    acc[i][j] = fmaf(a[i], b[j], acc[i][j]);
        }
        __syncthreads();
        if (t + 1 < ntiles) {
            commit();
            __syncthreads();
        }
    }

#pragma unroll
    for (int i = 0; i < TM; i++) {
        int gr = rowBase + trow * TM + i;
        if (gr >= M) continue;
        float dscale = 1.f;
        if (MODE == 1) dscale = rsqrtf((float)g_deg[r][gr] + 1.0f);
#pragma unroll
        for (int j = 0; j < TN; j++) {
            int gc = tcol * TN + j;
            float v = acc[i][j];
            if (MODE == 0) {
                g_h[(size_t)gr * BN + gc] = fmaxf(v + bias[gc], 0.f);
            } else if (MODE == 1) {
                g_hw[r][(size_t)gr * BN + gc] = v * dscale;
            } else {
                Cext[(size_t)gr * BN + gc] = v + bias[gc];
            }
        }
    }
}

// ---------------- CSR-build device bodies --------------------------------------
__device__ void count_body(const int* __restrict__ ei, int E, int bid, int nb) {
#pragma unroll
    for (int r = 0; r < NREL; r++) {
        const int* dst = ei + (size_t)(2 * r + 1) * E;
        for (int e = bid * 256 + (int)threadIdx.x; e < E; e += nb * 256) {
            int d = dst[e];
            if ((unsigned)d < NN) atomicAdd(&g_deg[r][d], 1);
        }
    }
}

__device__ void fill_body(const int* __restrict__ ei, int E, int bid, int nb) {
#pragma unroll
    for (int r = 0; r < NREL; r++) {
        const int* src = ei + (size_t)(2 * r) * E;
        const int* dst = src + E;
        for (int e = bid * 256 + (int)threadIdx.x; e < E; e += nb * 256) {
            int s = src[e], d = dst[e];
            if ((unsigned)d < NN && (unsigned)s < NN) {
                int pos = atomicAdd(&g_cur[r][d], 1);
                g_csr[r][pos] = s;
            }
        }
    }
}

// 256-thread block-sequential exclusive scan over one relation's degrees
__device__ void scan_body(int r) {
    __shared__ __align__(16) int wsum[8];
    __shared__ int carry;
    const int tid = threadIdx.x;
    const int lane = tid & 31;
    const int wid  = tid >> 5;
    if (tid == 0) carry = 0;
    __syncthreads();
    for (int base = 0; base < NN; base += 256) {
        int i = base + tid;
        int v = (i < NN) ? g_deg[r][i] : 0;
        int x = v;
#pragma unroll
        for (int o = 1; o < 32; o <<= 1) {
            int y = __shfl_up_sync(0xffffffffu, x, o);
            if (lane >= o) x += y;
        }
        if (lane == 31) wsum[wid] = x;
        __syncthreads();
        if (tid < 8) {
            int w = wsum[tid];
#pragma unroll
            for (int o = 1; o < 8; o <<= 1) {
                int y = __shfl_up_sync(0x000000ffu, w, o);
                if (tid >= o) w += y;
            }
            wsum[tid] = w;
        }
        __syncthreads();
        int excl = x - v + (wid > 0 ? wsum[wid - 1] : 0) + carry;
        if (i < NN) { g_off[r][i] = excl; g_cur[r][i] = excl; }
        int total = wsum[7];
        __syncthreads();
        if (tid == 0) carry += total;
        __syncthreads();
    }
    if (tid == 0) g_off[r][NN] = carry;
}

// ---------------- kernels -------------------------------------------------------
#define EMB_TILES 782   /* ceil(50000/64) */
#define REL_TILES 391   /* ceil(50000/128) */
#define CNT_BLKS  128
#define FILL_BLKS 192

__global__ void zero_deg_kernel() {
    int i = blockIdx.x * blockDim.x + threadIdx.x;
    if (i < NREL * NN) ((int*)g_deg)[i] = 0;
}

// K2: degree count (first 128 blocks — wave-1 start) + embedder GEMM
__global__ __launch_bounds__(256)
void k2_emb_count(const float* __restrict__ x, const float* __restrict__ emb_w,
                  const float* __restrict__ emb_b,
                  const int* __restrict__ ei, int E) {
    if (blockIdx.x < CNT_BLKS)
        count_body(ei, E, blockIdx.x, CNT_BLKS);
    else
        sgemm_body<64, 128, 20, 4, 8, 0>(x, emb_w, emb_b, nullptr, NN, 300, 0,
                                         blockIdx.x - CNT_BLKS);
}

// K3: offset scan (first 3 blocks) + relation GEMMs r=0,1
__global__ __launch_bounds__(256)
void k3_rel01_scan(const float* __restrict__ w) {
    int b = blockIdx.x;
    if (b < NREL) {
        scan_body(b);
    } else {
        b -= NREL;
        sgemm_body<128, 128, 16, 8, 8, 1>(nullptr, w, nullptr, nullptr, NN, HID,
                                          b / REL_TILES, b % REL_TILES);
    }
}

// K4: CSR fill (first 192 blocks) + relation GEMM r=2
__global__ __launch_bounds__(256)
void k4_rel2_fill(const float* __restrict__ w, const int* __restrict__ ei, int E) {
    if (blockIdx.x < FILL_BLKS)
        fill_body(ei, E, blockIdx.x, FILL_BLKS);
    else
        sgemm_body<128, 128, 16, 8, 8, 1>(nullptr, w, nullptr, nullptr, NN, HID,
                                          2, blockIdx.x - FILL_BLKS);
}

// plain relation-GEMM launch (layer 1, all 3 relations)
__global__ __launch_bounds__(256)
void rel_gemm_kernel(const float* __restrict__ w) {
    sgemm_body<128, 128, 16, 8, 8, 1>(nullptr, w, nullptr, nullptr, NN, HID,
                                      blockIdx.y, blockIdx.x);
}

// final linear
__global__ __launch_bounds__(256)
void fin_gemm_kernel(const float* __restrict__ w, const float* __restrict__ b,
                     float* __restrict__ out) {
    sgemm_body<128, 64, 16, 8, 4, 2>(nullptr, w, b, out, NN, HID, 0, blockIdx.x);
}

// ---------------- CSR gather: warp per node, fused self+bias+relu ------------
__launch_bounds__(256)
__global__ void gather_kernel(const float* __restrict__ bias) {
    const int node = (blockIdx.x * blockDim.x + threadIdx.x) >> 5;
    const int lane = threadIdx.x & 31;
    if (node >= NN) return;
    const int c0 = lane * 4;

    float4 tot;
    tot.x = bias[c0 + 0] + bias[HID + c0 + 0] + bias[2 * HID + c0 + 0];
    tot.y = bias[c0 + 1] + bias[HID + c0 + 1] + bias[2 * HID + c0 + 1];
    tot.z = bias[c0 + 2] + bias[HID + c0 + 2] + bias[2 * HID + c0 + 2];
    tot.w = bias[c0 + 3] + bias[HID + c0 + 3] + bias[2 * HID + c0 + 3];

#pragma unroll
    for (int r = 0; r < NREL; r++) {
        const float4* hw4 = (const float4*)g_hw[r];
        float4 a = hw4[(size_t)node * (HID / 4) + lane];   // self loop (pre-scaled)
        const int beg = g_off[r][node];
        const int end = g_off[r][node + 1];
        const int* __restrict__ csr = g_csr[r];
        for (int t = beg; t < end; t += 32) {
            int idx = (t + lane < end) ? csr[t + lane] : 0;
            int n = end - t; if (n > 32) n = 32;
            for (int j = 0; j < n; j++) {
                int s = __shfl_sync(0xffffffffu, idx, j);
                float4 v = hw4[(size_t)s * (HID / 4) + lane];
                a.x += v.x; a.y += v.y; a.z += v.z; a.w += v.w;
            }
        }
        float dd = rsqrtf((float)g_deg[r][node] + 1.0f);
        tot.x += a.x * dd; tot.y += a.y * dd;
        tot.z += a.z * dd; tot.w += a.w * dd;
    }
    tot.x = fmaxf(tot.x, 0.f);
    tot.y = fmaxf(tot.y, 0.f);
    tot.z = fmaxf(tot.z, 0.f);
    tot.w = fmaxf(tot.w, 0.f);
    ((float4*)g_h)[(size_t)node * (HID / 4) + lane] = tot;
}

// ---------------- launch ------------------------------------------------------
extern "C" void kernel_launch(void* const* d_in, const int* in_sizes, int n_in,
                              void* d_out, int out_size) {
    const float* x     = (const float*)d_in[0];
    const int*   ei    = (const int*)d_in[1];   // int32 (JAX x64 disabled)
    const float* emb_w = (const float*)d_in[2];
    const float* emb_b = (const float*)d_in[3];
    const float* w0    = (const float*)d_in[4];
    const float* b0    = (const float*)d_in[5];
    const float* w1    = (const float*)d_in[6];
    const float* b1    = (const float*)d_in[7];
    const float* lin_w = (const float*)d_in[8];
    const float* lin_b = (const float*)d_in[9];
    float* out = (float*)d_out;

    const int E = in_sizes[1] / (2 * NREL);
    const int gather_blocks = (NN * 32 + 255) / 256;   // warp per node

    // stage 1: zero degree counters
    zero_deg_kernel<<<(NREL * NN + 255) / 256, 256>>>();

    // stage 2: degree count || embedder GEMM
    k2_emb_count<<<CNT_BLKS + EMB_TILES, 256>>>(x, emb_w, emb_b, ei, E);

    // stage 3: offset scan || layer-0 relation GEMMs r=0,1
    k3_rel01_scan<<<NREL + 2 * REL_TILES, 256>>>(w0);

    // stage 4: CSR fill || layer-0 relation GEMM r=2
    k4_rel2_fill<<<FILL_BLKS + REL_TILES, 256>>>(w0, ei, E);

    // layer-0 aggregate
    gather_kernel<<<gather_blocks, 256>>>(b0);

    // layer 1
    rel_gemm_kernel<<<dim3(REL_TILES, NREL), 256>>>(w1);
    gather_kernel<<<gather_blocks, 256>>>(b1);

    // final linear
    fin_gemm_kernel<<<REL_TILES, 256>>>(lin_w, lin_b, out);
}

// round 12
// speedup vs baseline: 2.3020x; 1.0598x over previous
#include <cuda_runtime.h>
#include <cuda_fp16.h>
#include <stdint.h>

#define NN    50000
#define HID   128
#define NREL  3
#define EMAX  800000

// ---------------- scratch (device globals; 16B-aligned) ----------------------
__device__ __align__(16) float  g_h  [(size_t)NN * HID];       // current features (fp32)
__device__ __align__(16) __half g_hw [NREL][(size_t)NN * HID]; // (h @ w[r]) * dis[r], fp16
__device__ __align__(16) int    g_deg[NREL][NN];
__device__ __align__(16) int    g_off[NREL][NN + 1];           // CSR row offsets
__device__ __align__(16) int    g_cur[NREL][NN];               // fill cursors
__device__ __align__(16) int    g_csr[NREL][EMAX];             // src sorted by dst

// ---------------- GEMM body: single smem buffer + register prefetch -----------
// MODE 0: g_h    = relu(A @ B + bias)          (embedder)
// MODE 1: g_hw[r]= fp16( (g_h @ B[r]) * rsqrt(deg+1) )  (relation GEMMs)
// MODE 2: Cext   = g_h @ B + bias              (final linear)
// Requires: K % BK == 0, K % 4 == 0, BK % 4 == 0, A rows 16B-aligned, TN even.
template <int BM, int BN, int BK, int TM, int TN, int MODE>
__device__ __forceinline__ void sgemm_body(const float* __restrict__ Aext,
                                           const float* __restrict__ Bmat,
                                           const float* __restrict__ bias,
                                           float* __restrict__ Cext,
                                           int M, int K, int r, int tilex) {
    const float* A = (MODE == 0) ? Aext : g_h;
    const float* B = Bmat + (size_t)r * K * BN;

    // 16B alignment mandatory: hybrid kernels share smem layout with aux
    // branches whose small objects would otherwise shift the base.
    __shared__ __align__(16) float As[BK][BM + 4];   // transposed A tile
    __shared__ __align__(16) float Bs[BK][BN];

    const int tid  = threadIdx.x;
    constexpr int TC = BN / TN;
    const int trow = tid / TC;
    const int tcol = tid % TC;
    const int rowBase = tilex * BM;

    float acc[TM][TN];
#pragma unroll
    for (int i = 0; i < TM; i++)
#pragma unroll
        for (int j = 0; j < TN; j++) acc[i][j] = 0.f;

    constexpr int ACNT = BM * BK / 4;   // float4s per A tile
    constexpr int BCNT = BK * BN / 4;
    constexpr int AF4  = (ACNT + 255) / 256;
    constexpr int BF4  = (BCNT + 255) / 256;
    float4 va[AF4], vb[BF4];

    const int ntiles = K / BK;

    auto fetch = [&](int k0) {
#pragma unroll
        for (int v = 0; v < AF4; v++) {
            int g = tid + v * 256;
            if ((ACNT % 256 == 0) || g < ACNT) {
                int row = g / (BK / 4), c4 = g % (BK / 4);
                int gr = rowBase + row; if (gr >= M) gr = M - 1;
                va[v] = *(const float4*)&A[(size_t)gr * K + k0 + c4 * 4];
            }
        }
#pragma unroll
        for (int v = 0; v < BF4; v++) {
            int g = tid + v * 256;
            if ((BCNT % 256 == 0) || g < BCNT) {
                int row = g / (BN / 4), c4 = g % (BN / 4);
                vb[v] = *(const float4*)&B[(size_t)(k0 + row) * BN + c4 * 4];
            }
        }
    };
    auto commit = [&]() {
#pragma unroll
        for (int v = 0; v < AF4; v++) {
            int g = tid + v * 256;
            if ((ACNT % 256 == 0) || g < ACNT) {
                int row = g / (BK / 4), c4 = g % (BK / 4);
                As[c4 * 4 + 0][row] = va[v].x;
                As[c4 * 4 + 1][row] = va[v].y;
                As[c4 * 4 + 2][row] = va[v].z;
                As[c4 * 4 + 3][row] = va[v].w;
            }
        }
#pragma unroll
        for (int v = 0; v < BF4; v++) {
            int g = tid + v * 256;
            if ((BCNT % 256 == 0) || g < BCNT) {
                int row = g / (BN / 4), c4 = g % (BN / 4);
                *(float4*)&Bs[row][c4 * 4] = vb[v];
            }
        }
    };

    fetch(0);
    commit();
    __syncthreads();

    for (int t = 0; t < ntiles; t++) {
        if (t + 1 < ntiles) fetch((t + 1) * BK);
#pragma unroll
        for (int kk = 0; kk < BK; kk++) {
            float a[TM], b[TN];
#pragma unroll
            for (int i = 0; i < TM; i++) a[i] = As[kk][trow * TM + i];
#pragma unroll
            for (int j = 0; j < TN; j++) b[j] = Bs[kk][tcol * TN + j];
#pragma unroll
            for (int i = 0; i < TM; i++)
#pragma unroll
                for (int j = 0; j < TN; j++)
                    acc[i][j] = fmaf(a[i], b[j], acc[i][j]);
        }
        __syncthreads();
        if (t + 1 < ntiles) {
            commit();
            __syncthreads();
        }
    }

#pragma unroll
    for (int i = 0; i < TM; i++) {
        int gr = rowBase + trow * TM + i;
        if (gr >= M) continue;
        if (MODE == 1) {
            float dscale = rsqrtf((float)g_deg[r][gr] + 1.0f);
#pragma unroll
            for (int j = 0; j < TN; j += 2) {
                int gc = tcol * TN + j;
                __half2 hv = __floats2half2_rn(acc[i][j] * dscale,
                                               acc[i][j + 1] * dscale);
                *(__half2*)&g_hw[r][(size_t)gr * BN + gc] = hv;
            }
        } else {
#pragma unroll
            for (int j = 0; j < TN; j++) {
                int gc = tcol * TN + j;
                float v = acc[i][j];
                if (MODE == 0) {
                    g_h[(size_t)gr * BN + gc] = fmaxf(v + bias[gc], 0.f);
                } else {
                    Cext[(size_t)gr * BN + gc] = v + bias[gc];
                }
            }
        }
    }
}

// ---------------- CSR-build device bodies --------------------------------------
__device__ void count_body(const int* __restrict__ ei, int E, int bid, int nb) {
#pragma unroll
    for (int r = 0; r < NREL; r++) {
        const int* dst = ei + (size_t)(2 * r + 1) * E;
        for (int e = bid * 256 + (int)threadIdx.x; e < E; e += nb * 256) {
            int d = dst[e];
            if ((unsigned)d < NN) atomicAdd(&g_deg[r][d], 1);
        }
    }
}

__device__ void fill_body(const int* __restrict__ ei, int E, int bid, int nb) {
#pragma unroll
    for (int r = 0; r < NREL; r++) {
        const int* src = ei + (size_t)(2 * r) * E;
        const int* dst = src + E;
        for (int e = bid * 256 + (int)threadIdx.x; e < E; e += nb * 256) {
            int s = src[e], d = dst[e];
            if ((unsigned)d < NN && (unsigned)s < NN) {
                int pos = atomicAdd(&g_cur[r][d], 1);
                g_csr[r][pos] = s;
            }
        }
    }
}

// 256-thread block-sequential exclusive scan over one relation's degrees
__device__ void scan_body(int r) {
    __shared__ __align__(16) int wsum[8];
    __shared__ int carry;
    const int tid = threadIdx.x;
    const int lane = tid & 31;
    const int wid  = tid >> 5;
    if (tid == 0) carry = 0;
    __syncthreads();
    for (int base = 0; base < NN; base += 256) {
        int i = base + tid;
        int v = (i < NN) ? g_deg[r][i] : 0;
        int x = v;
#pragma unroll
        for (int o = 1; o < 32; o <<= 1) {
            int y = __shfl_up_sync(0xffffffffu, x, o);
            if (lane >= o) x += y;
        }
        if (lane == 31) wsum[wid] = x;
        __syncthreads();
        if (tid < 8) {
            int w = wsum[tid];
#pragma unroll
            for (int o = 1; o < 8; o <<= 1) {
                int y = __shfl_up_sync(0x000000ffu, w, o);
                if (tid >= o) w += y;
            }
            wsum[tid] = w;
        }
        __syncthreads();
        int excl = x - v + (wid > 0 ? wsum[wid - 1] : 0) + carry;
        if (i < NN) { g_off[r][i] = excl; g_cur[r][i] = excl; }
        int total = wsum[7];
        __syncthreads();
        if (tid == 0) carry += total;
        __syncthreads();
    }
    if (tid == 0) g_off[r][NN] = carry;
}

// ---------------- kernels -------------------------------------------------------
#define EMB_TILES 782   /* ceil(50000/64) */
#define REL_TILES 391   /* ceil(50000/128) */
#define CNT_BLKS  128
#define FILL_BLKS 192

__global__ void zero_deg_kernel() {
    int i = blockIdx.x * blockDim.x + threadIdx.x;
    if (i < NREL * NN) ((int*)g_deg)[i] = 0;
}

// K2: degree count (first 128 blocks — wave-1 start) + embedder GEMM
__global__ __launch_bounds__(256)
void k2_emb_count(const float* __restrict__ x, const float* __restrict__ emb_w,
                  const float* __restrict__ emb_b,
                  const int* __restrict__ ei, int E) {
    if (blockIdx.x < CNT_BLKS)
        count_body(ei, E, blockIdx.x, CNT_BLKS);
    else
        sgemm_body<64, 128, 20, 4, 8, 0>(x, emb_w, emb_b, nullptr, NN, 300, 0,
                                         blockIdx.x - CNT_BLKS);
}

// K3: offset scan (first 3 blocks) + relation GEMMs r=0,1
__global__ __launch_bounds__(256)
void k3_rel01_scan(const float* __restrict__ w) {
    int b = blockIdx.x;
    if (b < NREL) {
        scan_body(b);
    } else {
        b -= NREL;
        sgemm_body<128, 128, 16, 8, 8, 1>(nullptr, w, nullptr, nullptr, NN, HID,
                                          b / REL_TILES, b % REL_TILES);
    }
}

// K4: CSR fill (first 192 blocks) + relation GEMM r=2
__global__ __launch_bounds__(256)
void k4_rel2_fill(const float* __restrict__ w, const int* __restrict__ ei, int E) {
    if (blockIdx.x < FILL_BLKS)
        fill_body(ei, E, blockIdx.x, FILL_BLKS);
    else
        sgemm_body<128, 128, 16, 8, 8, 1>(nullptr, w, nullptr, nullptr, NN, HID,
                                          2, blockIdx.x - FILL_BLKS);
}

// plain relation-GEMM launch (layer 1, all 3 relations)
__global__ __launch_bounds__(256)
void rel_gemm_kernel(const float* __restrict__ w) {
    sgemm_body<128, 128, 16, 8, 8, 1>(nullptr, w, nullptr, nullptr, NN, HID,
                                      blockIdx.y, blockIdx.x);
}

// final linear
__global__ __launch_bounds__(256)
void fin_gemm_kernel(const float* __restrict__ w, const float* __restrict__ b,
                     float* __restrict__ out) {
    sgemm_body<128, 64, 16, 8, 4, 2>(nullptr, w, b, out, NN, HID, 0, blockIdx.x);
}

// ---------------- CSR gather: warp per node, fp16 messages, fused epilogue ----
__launch_bounds__(256)
__global__ void gather_kernel(const float* __restrict__ bias) {
    const int node = (blockIdx.x * blockDim.x + threadIdx.x) >> 5;
    const int lane = threadIdx.x & 31;
    if (node >= NN) return;
    const int c0 = lane * 4;

    float4 tot;
    tot.x = bias[c0 + 0] + bias[HID + c0 + 0] + bias[2 * HID + c0 + 0];
    tot.y = bias[c0 + 1] + bias[HID + c0 + 1] + bias[2 * HID + c0 + 1];
    tot.z = bias[c0 + 2] + bias[HID + c0 + 2] + bias[2 * HID + c0 + 2];
    tot.w = bias[c0 + 3] + bias[HID + c0 + 3] + bias[2 * HID + c0 + 3];

#pragma unroll
    for (int r = 0; r < NREL; r++) {
        const __half* hwr = g_hw[r];
        // self loop (pre-scaled): lane covers columns [lane*4, lane*4+4)
        float4 a;
        {
            uint2 raw = *(const uint2*)&hwr[(size_t)node * HID + c0];
            float2 f01 = __half22float2(*(__half2*)&raw.x);
            float2 f23 = __half22float2(*(__half2*)&raw.y);
            a.x = f01.x; a.y = f01.y; a.z = f23.x; a.w = f23.y;
        }
        const int beg = g_off[r][node];
        const int end = g_off[r][node + 1];
        const int* __restrict__ csr = g_csr[r];
        for (int t = beg; t < end; t += 32) {
            int idx = (t + lane < end) ? csr[t + lane] : 0;
            int n = end - t; if (n > 32) n = 32;
            for (int j = 0; j < n; j++) {
                int s = __shfl_sync(0xffffffffu, idx, j);
                uint2 raw = *(const uint2*)&hwr[(size_t)s * HID + c0];
                float2 f01 = __half22float2(*(__half2*)&raw.x);
                float2 f23 = __half22float2(*(__half2*)&raw.y);
                a.x += f01.x; a.y += f01.y; a.z += f23.x; a.w += f23.y;
            }
        }
        float dd = rsqrtf((float)g_deg[r][node] + 1.0f);
        tot.x += a.x * dd; tot.y += a.y * dd;
        tot.z += a.z * dd; tot.w += a.w * dd;
    }
    tot.x = fmaxf(tot.x, 0.f);
    tot.y = fmaxf(tot.y, 0.f);
    tot.z = fmaxf(tot.z, 0.f);
    tot.w = fmaxf(tot.w, 0.f);
    ((float4*)g_h)[(size_t)node * (HID / 4) + lane] = tot;
}

// ---------------- launch ------------------------------------------------------
extern "C" void kernel_launch(void* const* d_in, const int* in_sizes, int n_in,
                              void* d_out, int out_size) {
    const float* x     = (const float*)d_in[0];
    const int*   ei    = (const int*)d_in[1];   // int32 (JAX x64 disabled)
    const float* emb_w = (const float*)d_in[2];
    const float* emb_b = (const float*)d_in[3];
    const float* w0    = (const float*)d_in[4];
    const float* b0    = (const float*)d_in[5];
    const float* w1    = (const float*)d_in[6];
    const float* b1    = (const float*)d_in[7];
    const float* lin_w = (const float*)d_in[8];
    const float* lin_b = (const float*)d_in[9];
    float* out = (float*)d_out;

    const int E = in_sizes[1] / (2 * NREL);
    const int gather_blocks = (NN * 32 + 255) / 256;   // warp per node

    // stage 1: zero degree counters
    zero_deg_kernel<<<(NREL * NN + 255) / 256, 256>>>();

    // stage 2: degree count || embedder GEMM
    k2_emb_count<<<CNT_BLKS + EMB_TILES, 256>>>(x, emb_w, emb_b, ei, E);

    // stage 3: offset scan || layer-0 relation GEMMs r=0,1
    k3_rel01_scan<<<NREL + 2 * REL_TILES, 256>>>(w0);

    // stage 4: CSR fill || layer-0 relation GEMM r=2
    k4_rel2_fill<<<FILL_BLKS + REL_TILES, 256>>>(w0, ei, E);

    // layer-0 aggregate
    gather_kernel<<<gather_blocks, 256>>>(b0);

    // layer 1
    rel_gemm_kernel<<<dim3(REL_TILES, NREL), 256>>>(w1);
    gather_kernel<<<gather_blocks, 256>>>(b1);

    // final linear
    fin_gemm_kernel<<<REL_TILES, 256>>>(lin_w, lin_b, out);
}

// round 13
// speedup vs baseline: 2.4336x; 1.0572x over previous
#include <cuda_runtime.h>
#include <cuda_fp16.h>
#include <stdint.h>

#define NN    50000
#define HID   128
#define NREL  3
#define EMAX  800000

// ---------------- scratch (device globals; 16B-aligned) ----------------------
__device__ __align__(16) float  g_h  [(size_t)NN * HID];       // current features (fp32)
__device__ __align__(16) __half g_hw [NREL][(size_t)NN * HID]; // (h @ w[r]) * dis[r], fp16
__device__ __align__(16) int    g_deg[NREL][NN];
__device__ __align__(16) int    g_off[NREL][NN + 1];           // CSR row offsets
__device__ __align__(16) int    g_cur[NREL][NN];               // fill cursors
__device__ __align__(16) int    g_csr[NREL][EMAX];             // src sorted by dst

// ---------------- GEMM body: single smem buffer + register prefetch -----------
// MODE 0: g_h    = relu(A @ B + bias)          (embedder)
// MODE 1: g_hw[r]= fp16( (g_h @ B[r]) * rsqrt(deg+1) )  (relation GEMMs)
// MODE 2: Cext   = g_h @ B + bias              (final linear)
// Requires: K % BK == 0, K % 4 == 0, BK % 4 == 0, A rows 16B-aligned, TN even.
template <int BM, int BN, int BK, int TM, int TN, int MODE>
__device__ __forceinline__ void sgemm_body(const float* __restrict__ Aext,
                                           const float* __restrict__ Bmat,
                                           const float* __restrict__ bias,
                                           float* __restrict__ Cext,
                                           int M, int K, int r, int tilex) {
    const float* A = (MODE == 0) ? Aext : g_h;
    const float* B = Bmat + (size_t)r * K * BN;

    // 16B alignment mandatory: hybrid kernels share smem layout with aux
    // branches whose small objects would otherwise shift the base.
    __shared__ __align__(16) float As[BK][BM + 4];   // transposed A tile
    __shared__ __align__(16) float Bs[BK][BN];

    const int tid  = threadIdx.x;
    constexpr int TC = BN / TN;
    const int trow = tid / TC;
    const int tcol = tid % TC;
    const int rowBase = tilex * BM;

    float acc[TM][TN];
#pragma unroll
    for (int i = 0; i < TM; i++)
#pragma unroll
        for (int j = 0; j < TN; j++) acc[i][j] = 0.f;

    constexpr int ACNT = BM * BK / 4;   // float4s per A tile
    constexpr int BCNT = BK * BN / 4;
    constexpr int AF4  = (ACNT + 255) / 256;
    constexpr int BF4  = (BCNT + 255) / 256;
    float4 va[AF4], vb[BF4];

    const int ntiles = K / BK;

    auto fetch = [&](int k0) {
#pragma unroll
        for (int v = 0; v < AF4; v++) {
            int g = tid + v * 256;
            if ((ACNT % 256 == 0) || g < ACNT) {
                int row = g / (BK / 4), c4 = g % (BK / 4);
                int gr = rowBase + row; if (gr >= M) gr = M - 1;
                va[v] = *(const float4*)&A[(size_t)gr * K + k0 + c4 * 4];
            }
        }
#pragma unroll
        for (int v = 0; v < BF4; v++) {
            int g = tid + v * 256;
            if ((BCNT % 256 == 0) || g < BCNT) {
                int row = g / (BN / 4), c4 = g % (BN / 4);
                vb[v] = *(const float4*)&B[(size_t)(k0 + row) * BN + c4 * 4];
            }
        }
    };
    auto commit = [&]() {
#pragma unroll
        for (int v = 0; v < AF4; v++) {
            int g = tid + v * 256;
            if ((ACNT % 256 == 0) || g < ACNT) {
                int row = g / (BK / 4), c4 = g % (BK / 4);
                As[c4 * 4 + 0][row] = va[v].x;
                As[c4 * 4 + 1][row] = va[v].y;
                As[c4 * 4 + 2][row] = va[v].z;
                As[c4 * 4 + 3][row] = va[v].w;
            }
        }
#pragma unroll
        for (int v = 0; v < BF4; v++) {
            int g = tid + v * 256;
            if ((BCNT % 256 == 0) || g < BCNT) {
                int row = g / (BN / 4), c4 = g % (BN / 4);
                *(float4*)&Bs[row][c4 * 4] = vb[v];
            }
        }
    };

    fetch(0);
    commit();
    __syncthreads();

    for (int t = 0; t < ntiles; t++) {
        if (t + 1 < ntiles) fetch((t + 1) * BK);
#pragma unroll
        for (int kk = 0; kk < BK; kk++) {
            float a[TM], b[TN];
#pragma unroll
            for (int i = 0; i < TM; i++) a[i] = As[kk][trow * TM + i];
#pragma unroll
            for (int j = 0; j < TN; j++) b[j] = Bs[kk][tcol * TN + j];
#pragma unroll
            for (int i = 0; i < TM; i++)
#pragma unroll
                for (int j = 0; j < TN; j++)
                    acc[i][j] = fmaf(a[i], b[j], acc[i][j]);
        }
        __syncthreads();
        if (t + 1 < ntiles) {
            commit();
            __syncthreads();
        }
    }

#pragma unroll
    for (int i = 0; i < TM; i++) {
        int gr = rowBase + trow * TM + i;
        if (gr >= M) continue;
        if (MODE == 1) {
            float dscale = rsqrtf((float)g_deg[r][gr] + 1.0f);
#pragma unroll
            for (int j = 0; j < TN; j += 2) {
                int gc = tcol * TN + j;
                __half2 hv = __floats2half2_rn(acc[i][j] * dscale,
                                               acc[i][j + 1] * dscale);
                *(__half2*)&g_hw[r][(size_t)gr * BN + gc] = hv;
            }
        } else {
#pragma unroll
            for (int j = 0; j < TN; j++) {
                int gc = tcol * TN + j;
                float v = acc[i][j];
                if (MODE == 0) {
                    g_h[(size_t)gr * BN + gc] = fmaxf(v + bias[gc], 0.f);
                } else {
                    Cext[(size_t)gr * BN + gc] = v + bias[gc];
                }
            }
        }
    }
}

// ---------------- CSR-build device bodies --------------------------------------
__device__ void count_body(const int* __restrict__ ei, int E, int bid, int nb) {
#pragma unroll
    for (int r = 0; r < NREL; r++) {
        const int* dst = ei + (size_t)(2 * r + 1) * E;
        for (int e = bid * 256 + (int)threadIdx.x; e < E; e += nb * 256) {
            int d = dst[e];
            if ((unsigned)d < NN) atomicAdd(&g_deg[r][d], 1);
        }
    }
}

__device__ void fill_body(const int* __restrict__ ei, int E, int bid, int nb) {
#pragma unroll
    for (int r = 0; r < NREL; r++) {
        const int* src = ei + (size_t)(2 * r) * E;
        const int* dst = src + E;
        for (int e = bid * 256 + (int)threadIdx.x; e < E; e += nb * 256) {
            int s = src[e], d = dst[e];
            if ((unsigned)d < NN && (unsigned)s < NN) {
                int pos = atomicAdd(&g_cur[r][d], 1);
                g_csr[r][pos] = s;
            }
        }
    }
}

// 256-thread block-sequential exclusive scan over one relation's degrees
__device__ void scan_body(int r) {
    __shared__ __align__(16) int wsum[8];
    __shared__ int carry;
    const int tid = threadIdx.x;
    const int lane = tid & 31;
    const int wid  = tid >> 5;
    if (tid == 0) carry = 0;
    __syncthreads();
    for (int base = 0; base < NN; base += 256) {
        int i = base + tid;
        int v = (i < NN) ? g_deg[r][i] : 0;
        int x = v;
#pragma unroll
        for (int o = 1; o < 32; o <<= 1) {
            int y = __shfl_up_sync(0xffffffffu, x, o);
            if (lane >= o) x += y;
        }
        if (lane == 31) wsum[wid] = x;
        __syncthreads();
        if (tid < 8) {
            int w = wsum[tid];
#pragma unroll
            for (int o = 1; o < 8; o <<= 1) {
                int y = __shfl_up_sync(0x000000ffu, w, o);
                if (tid >= o) w += y;
            }
            wsum[tid] = w;
        }
        __syncthreads();
        int excl = x - v + (wid > 0 ? wsum[wid - 1] : 0) + carry;
        if (i < NN) { g_off[r][i] = excl; g_cur[r][i] = excl; }
        int total = wsum[7];
        __syncthreads();
        if (tid == 0) carry += total;
        __syncthreads();
    }
    if (tid == 0) g_off[r][NN] = carry;
}

// ---------------- kernels -------------------------------------------------------
#define EMB_TILES 782   /* ceil(50000/64) */
#define REL_TILES 391   /* ceil(50000/128) */
#define CNT_BLKS  128
#define FILL_BLKS 592

__global__ void zero_deg_kernel() {
    int i = blockIdx.x * blockDim.x + threadIdx.x;
    if (i < NREL * NN) ((int*)g_deg)[i] = 0;
}

// K2: degree count (first 128 blocks — wave-1 start) + embedder GEMM
__global__ __launch_bounds__(256)
void k2_emb_count(const float* __restrict__ x, const float* __restrict__ emb_w,
                  const float* __restrict__ emb_b,
                  const int* __restrict__ ei, int E) {
    if (blockIdx.x < CNT_BLKS)
        count_body(ei, E, blockIdx.x, CNT_BLKS);
    else
        sgemm_body<64, 128, 20, 4, 8, 0>(x, emb_w, emb_b, nullptr, NN, 300, 0,
                                         blockIdx.x - CNT_BLKS);
}

// K3: offset scan (first 3 blocks) + ALL THREE layer-0 relation GEMMs.
// 3 + 1173 blocks = 3.96 waves at 2 CTAs/SM — dense wave packing (vs the
// old rel01/rel2 split whose 1.32-wave tail wasted most of a wave).
__global__ __launch_bounds__(256)
void k3_rel_scan(const float* __restrict__ w) {
    int b = blockIdx.x;
    if (b < NREL) {
        scan_body(b);
    } else {
        b -= NREL;
        sgemm_body<128, 128, 16, 8, 8, 1>(nullptr, w, nullptr, nullptr, NN, HID,
                                          b / REL_TILES, b % REL_TILES);
    }
}

// K4: CSR fill alone, full chip
__global__ __launch_bounds__(256)
void k4_fill(const int* __restrict__ ei, int E) {
    fill_body(ei, E, blockIdx.x, FILL_BLKS);
}

// layer-1 relation GEMMs (all 3)
__global__ __launch_bounds__(256)
void rel_gemm_kernel(const float* __restrict__ w) {
    sgemm_body<128, 128, 16, 8, 8, 1>(nullptr, w, nullptr, nullptr, NN, HID,
                                      blockIdx.y, blockIdx.x);
}

// final linear
__global__ __launch_bounds__(256)
void fin_gemm_kernel(const float* __restrict__ w, const float* __restrict__ b,
                     float* __restrict__ out) {
    sgemm_body<128, 64, 16, 8, 4, 2>(nullptr, w, b, out, NN, HID, 0, blockIdx.x);
}

// ---------------- CSR gather: warp per node, fp16 messages, fused epilogue ----
__launch_bounds__(256)
__global__ void gather_kernel(const float* __restrict__ bias) {
    const int node = (blockIdx.x * blockDim.x + threadIdx.x) >> 5;
    const int lane = threadIdx.x & 31;
    if (node >= NN) return;
    const int c0 = lane * 4;

    float4 tot;
    tot.x = bias[c0 + 0] + bias[HID + c0 + 0] + bias[2 * HID + c0 + 0];
    tot.y = bias[c0 + 1] + bias[HID + c0 + 1] + bias[2 * HID + c0 + 1];
    tot.z = bias[c0 + 2] + bias[HID + c0 + 2] + bias[2 * HID + c0 + 2];
    tot.w = bias[c0 + 3] + bias[HID + c0 + 3] + bias[2 * HID + c0 + 3];

#pragma unroll
    for (int r = 0; r < NREL; r++) {
        const __half* hwr = g_hw[r];
        // self loop (pre-scaled): lane covers columns [lane*4, lane*4+4)
        float4 a;
        {
            uint2 raw = *(const uint2*)&hwr[(size_t)node * HID + c0];
            float2 f01 = __half22float2(*(__half2*)&raw.x);
            float2 f23 = __half22float2(*(__half2*)&raw.y);
            a.x = f01.x; a.y = f01.y; a.z = f23.x; a.w = f23.y;
        }
        const int beg = g_off[r][node];
        const int end = g_off[r][node + 1];
        const int* __restrict__ csr = g_csr[r];
        for (int t = beg; t < end; t += 32) {
            int idx = (t + lane < end) ? csr[t + lane] : 0;
            int n = end - t; if (n > 32) n = 32;
            for (int j = 0; j < n; j++) {
                int s = __shfl_sync(0xffffffffu, idx, j);
                uint2 raw = *(const uint2*)&hwr[(size_t)s * HID + c0];
                float2 f01 = __half22float2(*(__half2*)&raw.x);
                float2 f23 = __half22float2(*(__half2*)&raw.y);
                a.x += f01.x; a.y += f01.y; a.z += f23.x; a.w += f23.y;
            }
        }
        float dd = rsqrtf((float)g_deg[r][node] + 1.0f);
        tot.x += a.x * dd; tot.y += a.y * dd;
        tot.z += a.z * dd; tot.w += a.w * dd;
    }
    tot.x = fmaxf(tot.x, 0.f);
    tot.y = fmaxf(tot.y, 0.f);
    tot.z = fmaxf(tot.z, 0.f);
    tot.w = fmaxf(tot.w, 0.f);
    ((float4*)g_h)[(size_t)node * (HID / 4) + lane] = tot;
}

// ---------------- launch ------------------------------------------------------
extern "C" void kernel_launch(void* const* d_in, const int* in_sizes, int n_in,
                              void* d_out, int out_size) {
    const float* x     = (const float*)d_in[0];
    const int*   ei    = (const int*)d_in[1];   // int32 (JAX x64 disabled)
    const float* emb_w = (const float*)d_in[2];
    const float* emb_b = (const float*)d_in[3];
    const float* w0    = (const float*)d_in[4];
    const float* b0    = (const float*)d_in[5];
    const float* w1    = (const float*)d_in[6];
    const float* b1    = (const float*)d_in[7];
    const float* lin_w = (const float*)d_in[8];
    const float* lin_b = (const float*)d_in[9];
    float* out = (float*)d_out;

    const int E = in_sizes[1] / (2 * NREL);
    const int gather_blocks = (NN * 32 + 255) / 256;   // warp per node

    // stage 1: zero degree counters
    zero_deg_kernel<<<(NREL * NN + 255) / 256, 256>>>();

    // stage 2: degree count || embedder GEMM
    k2_emb_count<<<CNT_BLKS + EMB_TILES, 256>>>(x, emb_w, emb_b, ei, E);

    // stage 3: offset scan || layer-0 relation GEMMs (all 3 relations)
    k3_rel_scan<<<NREL + NREL * REL_TILES, 256>>>(w0);

    // stage 4: CSR fill (full chip)
    k4_fill<<<FILL_BLKS, 256>>>(ei, E);

    // layer-0 aggregate
    gather_kernel<<<gather_blocks, 256>>>(b0);

    // layer 1
    rel_gemm_kernel<<<dim3(REL_TILES, NREL), 256>>>(w1);
    gather_kernel<<<gather_blocks, 256>>>(b1);

    // final linear
    fin_gemm_kernel<<<REL_TILES, 256>>>(lin_w, lin_b, out);
}